// round 2
// baseline (speedup 1.0000x reference)
#include <cuda_runtime.h>
#include <mma.h>
#include <cstddef>

using namespace nvcuda;

#define BB 64
#define TT 512
#define DD 512
#define HH 768
#define NG 3072              // 4*H
#define MMROWS (BB * TT)     // 32768

// ---------------- scratch (device globals: the sanctioned scratch path) ----
__device__ float g_xp[(size_t)2 * MMROWS * NG];   // [dir][b*T + t][4H]  (805 MB)
__device__ float g_h[2][2][BB * HH];              // [dir][parity][b*H]
__device__ float g_c[2][BB * HH];                 // [dir][b*H]

__device__ __forceinline__ float sigmoidf(float x) {
    return 1.0f / (1.0f + expf(-x));
}

template <class Frag>
__device__ __forceinline__ void frag_to_tf32(Frag& f) {
#pragma unroll
    for (int i = 0; i < f.num_elements; i++)
        f.x[i] = wmma::__float_to_tf32(f.x[i]);
}

// ---------------------------------------------------------------------------
// init: zero h (parity 0) and c for both directions
// ---------------------------------------------------------------------------
__global__ void init_state() {
    int idx = blockIdx.x * 256 + threadIdx.x;
    if (idx < BB * HH) {
        g_h[0][0][idx] = 0.0f;
        g_h[1][0][idx] = 0.0f;
        g_c[0][idx] = 0.0f;
        g_c[1][idx] = 0.0f;
    }
}

// ---------------------------------------------------------------------------
// xproj: xp[dir][m, n] = seq[m, :] @ W_dir[0:D, n]     (bias added later)
// M = B*T = 32768, K = D = 512, N = 4H = 3072
// CTA tile 128x64, BK=16, 256 threads, tf32 WMMA 16x16x8.
// ---------------------------------------------------------------------------
__global__ void __launch_bounds__(256) xproj_kernel(
    const float* __restrict__ seq,
    const float* __restrict__ Wfw,
    const float* __restrict__ Wbw)
{
    const int dir = blockIdx.z;
    const float* W = dir ? Wbw : Wfw;
    float* xp = g_xp + (size_t)dir * MMROWS * NG;

    const int m0 = blockIdx.x * 128;
    const int n0 = blockIdx.y * 64;

    __shared__ __align__(16) float As[128][20];   // 128x16 tile (+pad)
    __shared__ __align__(16) float Bs[16][68];    // 16x64 tile (+pad)

    const int tid = threadIdx.x;
    const int w = tid >> 5;
    const int wm = w & 3;      // 4 row blocks of 32
    const int wn = w >> 2;     // 2 col blocks of 32

    wmma::fragment<wmma::accumulator, 16, 16, 8, float> acc[2][2];
#pragma unroll
    for (int i = 0; i < 2; i++)
#pragma unroll
        for (int j = 0; j < 2; j++)
            wmma::fill_fragment(acc[i][j], 0.0f);

    float ra[8], rb[4];
    // prefetch k-tile 0
#pragma unroll
    for (int e = 0; e < 8; e++) {
        int idx = e * 256 + tid; int r = idx >> 4, c = idx & 15;
        ra[e] = seq[(size_t)(m0 + r) * DD + c];
    }
#pragma unroll
    for (int e = 0; e < 4; e++) {
        int idx = e * 256 + tid; int r = idx >> 6, c = idx & 63;
        rb[e] = W[(size_t)r * NG + n0 + c];
    }

    for (int kt = 0; kt < DD / 16; kt++) {
        __syncthreads();
#pragma unroll
        for (int e = 0; e < 8; e++) {
            int idx = e * 256 + tid; int r = idx >> 4, c = idx & 15;
            As[r][c] = ra[e];
        }
#pragma unroll
        for (int e = 0; e < 4; e++) {
            int idx = e * 256 + tid; int r = idx >> 6, c = idx & 63;
            Bs[r][c] = rb[e];
        }
        __syncthreads();

        if (kt + 1 < DD / 16) {
            int k0 = (kt + 1) * 16;
#pragma unroll
            for (int e = 0; e < 8; e++) {
                int idx = e * 256 + tid; int r = idx >> 4, c = idx & 15;
                ra[e] = seq[(size_t)(m0 + r) * DD + k0 + c];
            }
#pragma unroll
            for (int e = 0; e < 4; e++) {
                int idx = e * 256 + tid; int r = idx >> 6, c = idx & 63;
                rb[e] = W[(size_t)(k0 + r) * NG + n0 + c];
            }
        }

#pragma unroll
        for (int k8 = 0; k8 < 16; k8 += 8) {
            wmma::fragment<wmma::matrix_a, 16, 16, 8, wmma::precision::tf32, wmma::row_major> af[2];
            wmma::fragment<wmma::matrix_b, 16, 16, 8, wmma::precision::tf32, wmma::row_major> bf[2];
#pragma unroll
            for (int fm = 0; fm < 2; fm++) {
                wmma::load_matrix_sync(af[fm], &As[wm * 32 + fm * 16][k8], 20);
                frag_to_tf32(af[fm]);
            }
#pragma unroll
            for (int fn = 0; fn < 2; fn++) {
                wmma::load_matrix_sync(bf[fn], &Bs[k8][wn * 32 + fn * 16], 68);
                frag_to_tf32(bf[fn]);
            }
#pragma unroll
            for (int fm = 0; fm < 2; fm++)
#pragma unroll
                for (int fn = 0; fn < 2; fn++)
                    wmma::mma_sync(acc[fm][fn], af[fm], bf[fn], acc[fm][fn]);
        }
    }

#pragma unroll
    for (int fm = 0; fm < 2; fm++)
#pragma unroll
        for (int fn = 0; fn < 2; fn++) {
            size_t row = m0 + wm * 32 + fm * 16;
            size_t col = n0 + wn * 32 + fn * 16;
            wmma::store_matrix_sync(xp + row * NG + col, acc[fm][fn], NG,
                                    wmma::mem_row_major);
        }
}

// ---------------------------------------------------------------------------
// One LSTM time step, both directions in one launch.
// grid = (24 j-blocks, 2 dirs), 256 threads.
// CTA: gates[64 batch, 4 gates x 32 cols] = h_prev[64,768] @ W[D:, cols]
// then fused cell update + masked output scatter.
// ---------------------------------------------------------------------------
__global__ void __launch_bounds__(256) lstm_step(
    int t, int parity,
    const int* __restrict__ seq_len,
    const float* __restrict__ Wfw, const float* __restrict__ bfw,
    const float* __restrict__ Wbw, const float* __restrict__ bbw,
    float* __restrict__ out)
{
    const int dir = blockIdx.y;
    const int jb = blockIdx.x;                 // 0..23, 32 h-cols each
    const float* W = dir ? Wbw : Wfw;
    const float* bias = dir ? bbw : bfw;
    const float* xp = g_xp + (size_t)dir * MMROWS * NG;
    const float* Hprev = g_h[dir][parity];
    float* Hnext = g_h[dir][parity ^ 1];
    float* Cst = g_c[dir];

    __shared__ __align__(16) char smem_raw[4 * 64 * 36 * 4];   // 36 KB
    float (*Hs)[36] = (float(*)[36])smem_raw;                      // 64x36
    float (*Bs)[32][20] = (float(*)[32][20])(smem_raw + 64 * 36 * 4); // 8x32x20
    float (*Gs)[64][36] = (float(*)[64][36])smem_raw;              // 4x64x36 (reuse)

    const int tid = threadIdx.x;
    const int w = tid >> 5, lane = tid & 31;
    const int g = w & 3;       // gate
    const int jh = w >> 2;     // which 16-col half of the 32-col j block
    const int colbase = g * HH + jb * 32 + jh * 16;

    wmma::fragment<wmma::accumulator, 16, 16, 8, float> acc[4];
#pragma unroll
    for (int fm = 0; fm < 4; fm++) wmma::fill_fragment(acc[fm], 0.0f);

    float ra[8], rb[16];
#pragma unroll
    for (int e = 0; e < 8; e++) {               // h tile: 64x32
        int idx = e * 256 + tid; int r = idx >> 5, c = idx & 31;
        ra[e] = Hprev[r * HH + c];
    }
#pragma unroll
    for (int e = 0; e < 16; e++) {              // W tile per warp: 32(k) x 16(n)
        int idx = e * 32 + lane; int kr = idx >> 4, c = idx & 15;
        rb[e] = W[(size_t)(DD + kr) * NG + colbase + c];
    }

    for (int kt = 0; kt < HH / 32; kt++) {      // 24 iterations
        __syncthreads();
#pragma unroll
        for (int e = 0; e < 8; e++) {
            int idx = e * 256 + tid; int r = idx >> 5, c = idx & 31;
            Hs[r][c] = ra[e];
        }
#pragma unroll
        for (int e = 0; e < 16; e++) {
            int idx = e * 32 + lane; int kr = idx >> 4, c = idx & 15;
            Bs[w][kr][c] = rb[e];
        }
        __syncthreads();

        if (kt + 1 < HH / 32) {
            int k0 = (kt + 1) * 32;
#pragma unroll
            for (int e = 0; e < 8; e++) {
                int idx = e * 256 + tid; int r = idx >> 5, c = idx & 31;
                ra[e] = Hprev[r * HH + k0 + c];
            }
#pragma unroll
            for (int e = 0; e < 16; e++) {
                int idx = e * 32 + lane; int kr = idx >> 4, c = idx & 15;
                rb[e] = W[(size_t)(DD + k0 + kr) * NG + colbase + c];
            }
        }

#pragma unroll
        for (int k4 = 0; k4 < 4; k4++) {
            wmma::fragment<wmma::matrix_b, 16, 16, 8, wmma::precision::tf32, wmma::row_major> bf;
            wmma::load_matrix_sync(bf, &Bs[w][k4 * 8][0], 20);
            frag_to_tf32(bf);
#pragma unroll
            for (int fm = 0; fm < 4; fm++) {
                wmma::fragment<wmma::matrix_a, 16, 16, 8, wmma::precision::tf32, wmma::row_major> af;
                wmma::load_matrix_sync(af, &Hs[fm * 16][k4 * 8], 36);
                frag_to_tf32(af);
                wmma::mma_sync(acc[fm], af, bf, acc[fm]);
            }
        }
    }

    __syncthreads();   // all mma reads of Hs/Bs done; safe to overwrite with Gs
#pragma unroll
    for (int fm = 0; fm < 4; fm++)
        wmma::store_matrix_sync(&Gs[g][fm * 16][jh * 16], acc[fm], 36,
                                wmma::mem_row_major);
    __syncthreads();

    // fused cell update: 64 x 32 elements, 8 per thread
#pragma unroll
    for (int e = 0; e < 8; e++) {
        int idx = e * 256 + tid;
        int b = idx >> 5, j = idx & 31;
        int jg = jb * 32 + j;
        int L = seq_len[b];
        bool act = (t < L);
        int tx = dir ? (act ? (L - 1 - t) : t) : t;   // reversed input index (bw)

        size_t xrow = ((size_t)b * TT + tx) * NG;
        float gi = Gs[0][b][j] + xp[xrow + 0 * HH + jg] + bias[0 * HH + jg];
        float gj = Gs[1][b][j] + xp[xrow + 1 * HH + jg] + bias[1 * HH + jg];
        float gf = Gs[2][b][j] + xp[xrow + 2 * HH + jg] + bias[2 * HH + jg];
        float go = Gs[3][b][j] + xp[xrow + 3 * HH + jg] + bias[3 * HH + jg];

        float c = Cst[b * HH + jg];
        float nc = c * sigmoidf(gf + 1.0f) + sigmoidf(gi) * tanhf(gj);
        float nh = tanhf(nc) * sigmoidf(go);
        float hp = Hprev[b * HH + jg];

        Cst[b * HH + jg] = act ? nc : c;
        Hnext[b * HH + jg] = act ? nh : hp;

        int tout = (dir && act) ? (L - 1 - t) : t;    // reverse_sequence scatter
        float ov = act ? nh : 0.0f;                   // dynamic_rnn zeros
        out[((size_t)b * TT + tout) * (2 * HH) + dir * HH + jg] = ov;
    }
}

// ---------------------------------------------------------------------------
// finalize: state_h = concat(h_fw, h_bw) appended after outputs
// ---------------------------------------------------------------------------
__global__ void finalize(float* __restrict__ out) {
    int idx = blockIdx.x * 256 + threadIdx.x;
    if (idx < 2 * BB * HH) {
        int b = idx / (2 * HH);
        int r = idx % (2 * HH);
        int dir = r / HH;
        int j = r % HH;
        // after 512 steps the final h lives in parity 0
        out[(size_t)BB * TT * 2 * HH + idx] = g_h[dir][0][b * HH + j];
    }
}

// ---------------------------------------------------------------------------
extern "C" void kernel_launch(void* const* d_in, const int* in_sizes, int n_in,
                              void* d_out, int out_size)
{
    const float* seq     = (const float*)d_in[0];
    const int*   seq_len = (const int*)d_in[1];
    const float* Wfw     = (const float*)d_in[2];
    const float* bfw     = (const float*)d_in[3];
    const float* Wbw     = (const float*)d_in[4];
    const float* bbw     = (const float*)d_in[5];
    float* out = (float*)d_out;

    init_state<<<(BB * HH + 255) / 256, 256>>>();

    xproj_kernel<<<dim3(MMROWS / 128, NG / 64, 2), 256>>>(seq, Wfw, Wbw);

    for (int t = 0; t < TT; t++) {
        lstm_step<<<dim3(HH / 32, 2), 256>>>(t, t & 1, seq_len,
                                             Wfw, bfw, Wbw, bbw, out);
    }

    finalize<<<(2 * BB * HH + 255) / 256, 256>>>(out);
}

// round 3
// speedup vs baseline: 2.1353x; 2.1353x over previous
#include <cuda_runtime.h>
#include <mma.h>
#include <cstddef>
#include <cstdint>

using namespace nvcuda;

#define BB 64
#define TT 512
#define DD 512
#define HH 768
#define NG 3072              // 4*H
#define MMROWS (BB * TT)     // 32768
#define NCTA 96              // 2 dirs x 48 column blocks
#define WS_LD 68             // Ws row pad (64 cols + 4)
#define HS_LD 36             // Hs chunk row pad (32 + 4)
#define GS_LD 68

// ---------------- scratch (device globals: the sanctioned scratch path) ----
__device__ float g_xp[(size_t)2 * MMROWS * NG];   // [dir][b*T + t][4H]
__device__ float g_h[2][2][BB * HH];              // [dir][parity][b*H]
__device__ unsigned g_bar_count;
__device__ unsigned g_bar_gen;

__device__ __forceinline__ float sigmoidf(float x) {
    return 1.0f / (1.0f + expf(-x));
}

// ---------------------------------------------------------------------------
// software grid barrier (all NCTA CTAs guaranteed co-resident: 1 CTA/SM)
// ---------------------------------------------------------------------------
__device__ __forceinline__ void grid_sync() {
    __syncthreads();
    if (threadIdx.x == 0) {
        unsigned gen = *((volatile unsigned*)&g_bar_gen);
        __threadfence();
        unsigned arr = atomicAdd(&g_bar_count, 1u);
        if (arr == NCTA - 1) {
            g_bar_count = 0;
            __threadfence();
            atomicAdd(&g_bar_gen, 1u);
        } else {
            while (*((volatile unsigned*)&g_bar_gen) == gen)
                __nanosleep(40);
        }
        __threadfence();
    }
    __syncthreads();
}

// ---------------------------------------------------------------------------
// xproj: xp[dir][m, n] = seq[m, :] @ W_dir[0:D, n]
// M = 32768, K = 512, N = 3072. CTA tile 128x64, tf32 WMMA.
// ---------------------------------------------------------------------------
__global__ void __launch_bounds__(256) xproj_kernel(
    const float* __restrict__ seq,
    const float* __restrict__ Wfw,
    const float* __restrict__ Wbw)
{
    const int dir = blockIdx.z;
    const float* W = dir ? Wbw : Wfw;
    float* xp = g_xp + (size_t)dir * MMROWS * NG;

    const int m0 = blockIdx.x * 128;
    const int n0 = blockIdx.y * 64;

    __shared__ __align__(16) float As[128][20];
    __shared__ __align__(16) float Bs[16][68];

    const int tid = threadIdx.x;
    const int w = tid >> 5;
    const int wm = w & 3;
    const int wn = w >> 2;

    wmma::fragment<wmma::accumulator, 16, 16, 8, float> acc[2][2];
#pragma unroll
    for (int i = 0; i < 2; i++)
#pragma unroll
        for (int j = 0; j < 2; j++)
            wmma::fill_fragment(acc[i][j], 0.0f);

    float ra[8], rb[4];
#pragma unroll
    for (int e = 0; e < 8; e++) {
        int idx = e * 256 + tid; int r = idx >> 4, c = idx & 15;
        ra[e] = seq[(size_t)(m0 + r) * DD + c];
    }
#pragma unroll
    for (int e = 0; e < 4; e++) {
        int idx = e * 256 + tid; int r = idx >> 6, c = idx & 63;
        rb[e] = W[(size_t)r * NG + n0 + c];
    }

    for (int kt = 0; kt < DD / 16; kt++) {
        __syncthreads();
#pragma unroll
        for (int e = 0; e < 8; e++) {
            int idx = e * 256 + tid; int r = idx >> 4, c = idx & 15;
            As[r][c] = ra[e];
        }
#pragma unroll
        for (int e = 0; e < 4; e++) {
            int idx = e * 256 + tid; int r = idx >> 6, c = idx & 63;
            Bs[r][c] = rb[e];
        }
        __syncthreads();

        if (kt + 1 < DD / 16) {
            int k0 = (kt + 1) * 16;
#pragma unroll
            for (int e = 0; e < 8; e++) {
                int idx = e * 256 + tid; int r = idx >> 4, c = idx & 15;
                ra[e] = seq[(size_t)(m0 + r) * DD + k0 + c];
            }
#pragma unroll
            for (int e = 0; e < 4; e++) {
                int idx = e * 256 + tid; int r = idx >> 6, c = idx & 63;
                rb[e] = W[(size_t)(k0 + r) * NG + n0 + c];
            }
        }

#pragma unroll
        for (int k8 = 0; k8 < 16; k8 += 8) {
            wmma::fragment<wmma::matrix_a, 16, 16, 8, wmma::precision::tf32, wmma::row_major> af[2];
            wmma::fragment<wmma::matrix_b, 16, 16, 8, wmma::precision::tf32, wmma::row_major> bf[2];
#pragma unroll
            for (int fm = 0; fm < 2; fm++) {
                wmma::load_matrix_sync(af[fm], &As[wm * 32 + fm * 16][k8], 20);
#pragma unroll
                for (int i = 0; i < af[fm].num_elements; i++)
                    af[fm].x[i] = wmma::__float_to_tf32(af[fm].x[i]);
            }
#pragma unroll
            for (int fn = 0; fn < 2; fn++) {
                wmma::load_matrix_sync(bf[fn], &Bs[k8][wn * 32 + fn * 16], 68);
#pragma unroll
                for (int i = 0; i < bf[fn].num_elements; i++)
                    bf[fn].x[i] = wmma::__float_to_tf32(bf[fn].x[i]);
            }
#pragma unroll
            for (int fm = 0; fm < 2; fm++)
#pragma unroll
                for (int fn = 0; fn < 2; fn++)
                    wmma::mma_sync(acc[fm][fn], af[fm], bf[fn], acc[fm][fn]);
        }
    }

#pragma unroll
    for (int fm = 0; fm < 2; fm++)
#pragma unroll
        for (int fn = 0; fn < 2; fn++) {
            size_t row = m0 + wm * 32 + fm * 16;
            size_t col = n0 + wn * 32 + fn * 16;
            wmma::store_matrix_sync(xp + row * NG + col, acc[fm][fn], NG,
                                    wmma::mem_row_major);
        }
}

// ---------------------------------------------------------------------------
// cp.async 16B helper
// ---------------------------------------------------------------------------
__device__ __forceinline__ void cp16(float* smem_dst, const float* gmem_src) {
    unsigned d = (unsigned)__cvta_generic_to_shared(smem_dst);
    asm volatile("cp.async.ca.shared.global [%0], [%1], 16;\n"
                 :: "r"(d), "l"(gmem_src));
}

// ---------------------------------------------------------------------------
// Persistent recurrence kernel.
// grid = 96 CTAs (dir = bx/48, jb = bx%48 owns h-cols [jb*16, jb*16+16)).
// Per CTA: recurrent W slice (768 x 64 gate-cols, tf32) resident in smem.
// Per step: stream h via double-buffered cp.async, 64x64x768 WMMA,
// fused cell update with c/h carried in registers, software grid barrier.
// ---------------------------------------------------------------------------
__global__ void __launch_bounds__(512, 1) lstm_persistent(
    const int* __restrict__ seq_len,
    const float* __restrict__ Wfw, const float* __restrict__ bfw,
    const float* __restrict__ Wbw, const float* __restrict__ bbw,
    float* __restrict__ out)
{
    const int dir = blockIdx.x / 48;
    const int jb  = blockIdx.x % 48;
    const float* W    = dir ? Wbw : Wfw;
    const float* bias = dir ? bbw : bfw;
    const float* xp = g_xp + (size_t)dir * MMROWS * NG;

    extern __shared__ float smem[];
    float* Ws = smem;                       // [768][WS_LD]
    float* Hs = smem + 768 * WS_LD;         // [2][64][HS_LD]
    float* Gs = Hs;                         // [64][GS_LD] overlay (post-mainloop)
    __shared__ float bs[64];

    const int tid = threadIdx.x;
    const int w  = tid >> 5;
    const int wm = w & 3;      // 16-row (batch) block
    const int wn = w >> 2;     // 16-col (gate) block

    // --- one-time: load + tf32-round recurrent weight slice ---
    for (int i = tid; i < 768 * 64; i += 512) {
        int k = i >> 6, n = i & 63;
        int g = n >> 4, c = n & 15;
        float v = W[(size_t)(DD + k) * NG + g * HH + jb * 16 + c];
        Ws[k * WS_LD + n] = wmma::__float_to_tf32(v);
    }
    if (tid < 64) {
        int g = tid >> 4, c = tid & 15;
        bs[tid] = bias[g * HH + jb * 16 + c];
    }

    // --- per-thread cell ownership: (b, j) fixed for the whole run ---
    const int j  = tid & 15;
    const int jg = jb * 16 + j;
    const int bb0 = tid >> 4;       // 0..31
    const int bb1 = bb0 + 32;       // 32..63
    const int L0 = seq_len[bb0];
    const int L1 = seq_len[bb1];
    float c0 = 0.f, c1 = 0.f, h0 = 0.f, h1 = 0.f;

    // zero h parity-0 for our columns (everyone reads full h next)
    g_h[dir][0][bb0 * HH + jg] = 0.f;
    g_h[dir][0][bb1 * HH + jg] = 0.f;

    // chunk-copy thread mapping: 64 rows x 32 cols = 512 x (1 float4)
    const int cr = tid >> 3;
    const int cc = (tid & 7) * 4;

    grid_sync();

    for (int t = 0; t < TT; t++) {
        const int parr = t & 1;
        const float* hsrc = g_h[dir][parr];
        float* hdst = g_h[dir][parr ^ 1];

        // xp operand prefetch (in flight across the mainloop)
        const bool a0 = t < L0, a1 = t < L1;
        const int tx0 = dir ? (a0 ? L0 - 1 - t : t) : t;
        const int tx1 = dir ? (a1 ? L1 - 1 - t : t) : t;
        const float* x0 = xp + ((size_t)bb0 * TT + tx0) * NG + jg;
        const float* x1 = xp + ((size_t)bb1 * TT + tx1) * NG + jg;
        float xv00 = x0[0], xv01 = x0[HH], xv02 = x0[2 * HH], xv03 = x0[3 * HH];
        float xv10 = x1[0], xv11 = x1[HH], xv12 = x1[2 * HH], xv13 = x1[3 * HH];

        wmma::fragment<wmma::accumulator, 16, 16, 8, float> acc;
        wmma::fill_fragment(acc, 0.f);

        // prefetch chunks 0,1
        cp16(Hs + 0 * 64 * HS_LD + cr * HS_LD + cc, hsrc + cr * HH + 0 + cc);
        asm volatile("cp.async.commit_group;\n");
        cp16(Hs + 1 * 64 * HS_LD + cr * HS_LD + cc, hsrc + cr * HH + 32 + cc);
        asm volatile("cp.async.commit_group;\n");

        for (int ck = 0; ck < 24; ck++) {
            if (ck < 23) asm volatile("cp.async.wait_group 1;\n");
            else         asm volatile("cp.async.wait_group 0;\n");
            __syncthreads();
            float* Hb = Hs + (ck & 1) * 64 * HS_LD;
#pragma unroll
            for (int k8 = 0; k8 < 4; k8++) {
                wmma::fragment<wmma::matrix_a, 16, 16, 8, wmma::precision::tf32, wmma::row_major> af;
                wmma::load_matrix_sync(af, Hb + (wm * 16) * HS_LD + k8 * 8, HS_LD);
#pragma unroll
                for (int i = 0; i < af.num_elements; i++)
                    af.x[i] = wmma::__float_to_tf32(af.x[i]);
                wmma::fragment<wmma::matrix_b, 16, 16, 8, wmma::precision::tf32, wmma::row_major> bf;
                // Ws pre-rounded to tf32 -> no per-use conversion needed
                wmma::load_matrix_sync(bf, Ws + (ck * 32 + k8 * 8) * WS_LD + wn * 16, WS_LD);
                wmma::mma_sync(acc, af, bf, acc);
            }
            __syncthreads();
            if (ck + 2 < 24) {
                cp16(Hs + (ck & 1) * 64 * HS_LD + cr * HS_LD + cc,
                     hsrc + cr * HH + (ck + 2) * 32 + cc);
                asm volatile("cp.async.commit_group;\n");
            }
        }

        // stage gates into smem (overlays Hs; all mma done + synced)
        wmma::store_matrix_sync(Gs + (wm * 16) * GS_LD + wn * 16, acc, GS_LD,
                                wmma::mem_row_major);
        __syncthreads();

        // fused cell update (registers carry c and h)
        {
            float gi = Gs[bb0 * GS_LD +  0 + j] + xv00 + bs[j];
            float gj = Gs[bb0 * GS_LD + 16 + j] + xv01 + bs[16 + j];
            float gf = Gs[bb0 * GS_LD + 32 + j] + xv02 + bs[32 + j];
            float go = Gs[bb0 * GS_LD + 48 + j] + xv03 + bs[48 + j];
            float nc = c0 * sigmoidf(gf + 1.f) + sigmoidf(gi) * tanhf(gj);
            float nh = tanhf(nc) * sigmoidf(go);
            if (a0) { c0 = nc; h0 = nh; }
            int to = (dir && a0) ? (L0 - 1 - t) : t;
            out[((size_t)bb0 * TT + to) * (2 * HH) + dir * HH + jg] = a0 ? nh : 0.f;
            hdst[bb0 * HH + jg] = h0;
        }
        {
            float gi = Gs[bb1 * GS_LD +  0 + j] + xv10 + bs[j];
            float gj = Gs[bb1 * GS_LD + 16 + j] + xv11 + bs[16 + j];
            float gf = Gs[bb1 * GS_LD + 32 + j] + xv12 + bs[32 + j];
            float go = Gs[bb1 * GS_LD + 48 + j] + xv13 + bs[48 + j];
            float nc = c1 * sigmoidf(gf + 1.f) + sigmoidf(gi) * tanhf(gj);
            float nh = tanhf(nc) * sigmoidf(go);
            if (a1) { c1 = nc; h1 = nh; }
            int to = (dir && a1) ? (L1 - 1 - t) : t;
            out[((size_t)bb1 * TT + to) * (2 * HH) + dir * HH + jg] = a1 ? nh : 0.f;
            hdst[bb1 * HH + jg] = h1;
        }

        __threadfence();
        grid_sync();
    }

    // final state_h = concat(h_fw, h_bw), appended after outputs
    out[(size_t)BB * TT * 2 * HH + (size_t)bb0 * 2 * HH + dir * HH + jg] = h0;
    out[(size_t)BB * TT * 2 * HH + (size_t)bb1 * 2 * HH + dir * HH + jg] = h1;
}

// ---------------------------------------------------------------------------
extern "C" void kernel_launch(void* const* d_in, const int* in_sizes, int n_in,
                              void* d_out, int out_size)
{
    const float* seq     = (const float*)d_in[0];
    const int*   seq_len = (const int*)d_in[1];
    const float* Wfw     = (const float*)d_in[2];
    const float* bfw     = (const float*)d_in[3];
    const float* Wbw     = (const float*)d_in[4];
    const float* bbw     = (const float*)d_in[5];
    float* out = (float*)d_out;

    const int smem_bytes = (768 * WS_LD + 2 * 64 * HS_LD) * 4;  // 227328
    cudaFuncSetAttribute(lstm_persistent,
                         cudaFuncAttributeMaxDynamicSharedMemorySize, smem_bytes);

    xproj_kernel<<<dim3(MMROWS / 128, NG / 64, 2), 256>>>(seq, Wfw, Wbw);

    lstm_persistent<<<NCTA, 512, smem_bytes>>>(seq_len, Wfw, bfw, Wbw, bbw, out);
}